// round 16
// baseline (speedup 1.0000x reference)
#include <cuda_runtime.h>
#include <cuda_bf16.h>

#define VOCAB   16384
#define WIDTH   256
#define NTOK    8224      // 32 * 257
#define MPAD    8320      // 65 * 128
#define NBATCH  32

#define KTOT    512       // stored per row: [hi(256) | lo(256)]
#define TM      128
#define TN      128
#define NSLAB   12        // 4x hi*hi + 4x hi*lo + 4x lo*hi
#define STAGE   32768     // A 16KB + B 16KB
#define B_OFF   16384
#define NSTAGE  3
#define DYN_SMEM (NSTAGE * STAGE)   // 96KB -> 2 CTAs/SM

// ---------------- scratch (device globals; no runtime alloc) ----------------
__device__ __align__(16) __nv_bfloat16 g_Abf[MPAD * KTOT];    // 8.5 MB
__device__ __align__(16) __nv_bfloat16 g_Bbf[VOCAB * KTOT];   // 16.8 MB
__device__ unsigned long long  g_best[NTOK];
__device__ int                 g_used[VOCAB];
__device__ double              g_loss;
__device__ unsigned            g_done;

// ---------------- helpers ----------------
__device__ __forceinline__ float block_reduce_sum_256(float v) {
    __shared__ float red[8];
    const int lane = threadIdx.x & 31;
    const int w    = threadIdx.x >> 5;
    #pragma unroll
    for (int o = 16; o > 0; o >>= 1) v += __shfl_xor_sync(0xffffffffu, v, o);
    if (lane == 0) red[w] = v;
    __syncthreads();
    float s = 0.f;
    #pragma unroll
    for (int i = 0; i < 8; i++) s += red[i];
    return s;
}
__device__ __forceinline__ unsigned int f2key(float v) {
    unsigned int u = __float_as_uint(v);
    return (u & 0x80000000u) ? ~u : (u | 0x80000000u);
}
__device__ __forceinline__ unsigned smem_u32(const void* p) {
    unsigned a;
    asm("{ .reg .u64 t; cvta.to.shared.u64 t, %1; cvt.u32.u64 %0, t; }" : "=r"(a) : "l"(p));
    return a;
}
__device__ __forceinline__ void cp16(unsigned dst, const void* src) {
    asm volatile("cp.async.cg.shared.global [%0], [%1], 16;" :: "r"(dst), "l"(src));
}
#define CP_COMMIT() asm volatile("cp.async.commit_group;" ::: "memory")
#define CP_WAIT1()  asm volatile("cp.async.wait_group 1;"  ::: "memory")
#define CP_WAIT0()  asm volatile("cp.async.wait_group 0;"  ::: "memory")

__device__ __forceinline__ void ldsm4(unsigned& r0, unsigned& r1, unsigned& r2, unsigned& r3,
                                      unsigned addr) {
    asm volatile("ldmatrix.sync.aligned.m8n8.x4.shared.b16 {%0,%1,%2,%3}, [%4];"
                 : "=r"(r0), "=r"(r1), "=r"(r2), "=r"(r3) : "r"(addr));
}
__device__ __forceinline__ void mma_bf16(float* d, const unsigned* a, const unsigned* b) {
    asm volatile(
        "mma.sync.aligned.m16n8k16.row.col.f32.bf16.bf16.f32 "
        "{%0,%1,%2,%3}, {%4,%5,%6,%7}, {%8,%9}, {%0,%1,%2,%3};"
        : "+f"(d[0]), "+f"(d[1]), "+f"(d[2]), "+f"(d[3])
        : "r"(a[0]), "r"(a[1]), "r"(a[2]), "r"(a[3]), "r"(b[0]), "r"(b[1]));
}

// slab t -> (A k-offset, B k-offset) in bf16 elements within a row
__device__ __forceinline__ void slab_off(int t, int& kA, int& kB) {
    kA = (t < 8) ? ((t & 3) << 6) : (((t - 8) << 6) + 256);            // hi,hi,lo
    kB = (t < 4) ? (t << 6) : ((t < 8) ? (((t - 4) << 6) + 256)        // hi,lo,hi
                                       : ((t - 8) << 6));
}

// ---------------- K1: gather + normalize + bf16 hi/lo split (+ state reset) ----------------
// grid: [0,256) patch tile blocks (b, jg); [256,288) class tokens; [288,384) zero pad rows;
//       [384, 384+VOCAB) codebook rows.
__global__ void k_normalize(const float* __restrict__ cls,
                            const float* __restrict__ patch,
                            const float* __restrict__ W) {
    const int g   = blockIdx.x;
    const int tid = threadIdx.x;

    if (g < 256) {
        // ---- patch tokens: coalesced along j (two passes), smem transpose ----
        __shared__ float s_part[8][32];
        __shared__ float s_inv[32];
        __shared__ __nv_bfloat16 s_row[32][514];   // 257-word row stride: conflict-free
        const int b  = g >> 3;
        const int j0 = (g & 7) * 32;
        const int w = tid >> 5, lane = tid & 31;
        // fold g_best reset here (256*256 threads cover NTOK)
        const int gid = g * 256 + tid;
        if (gid < NTOK) g_best[gid] = 0ull;

        const float* psrc = patch + b * 65536 + j0;   // (c, j0+lane) at c*256 + lane
        float ss = 0.f;
        #pragma unroll 4
        for (int i = 0; i < 32; i++) {
            const float v = psrc[(w * 32 + i) * 256 + lane];
            ss += v * v;
        }
        s_part[w][lane] = ss;
        __syncthreads();
        if (w == 0) {
            float t = 0.f;
            #pragma unroll
            for (int i = 0; i < 8; i++) t += s_part[i][lane];
            s_inv[lane] = 1.f / fmaxf(sqrtf(t), 1e-12f);
        }
        __syncthreads();
        const float inv = s_inv[lane];
        #pragma unroll 4
        for (int i = 0; i < 32; i++) {
            const int c = w * 32 + i;
            const float v  = psrc[c * 256 + lane];
            const float xn = v * inv;
            const __nv_bfloat16 hi = __float2bfloat16(xn);
            const float lo = xn - __bfloat162float(hi);
            s_row[lane][c]       = hi;
            s_row[lane][256 + c] = __float2bfloat16(lo);
        }
        __syncthreads();
        // 32 contiguous A rows: linear coalesced copy (1 word/thread/row)
        unsigned* dw = (unsigned*)(g_Abf + (long long)(b * 257 + 1 + j0) * KTOT);
        #pragma unroll 8
        for (int row = 0; row < 32; row++)
            dw[row * 256 + tid] = *(const unsigned*)&s_row[row][tid * 2];
        return;
    }

    if (g < 288) {
        // ---- class tokens (32 rows, tiny) ----
        const int b = g - 256;
        const int c = tid;
        if (b == 0) {
            if (c == 1) g_loss = 0.0;
            if (c == 2) g_done = 0u;
        }
        const float v   = cls[b * WIDTH + c];
        const float s   = block_reduce_sum_256(v * v);
        const float inv = 1.f / fmaxf(sqrtf(s), 1e-12f);
        const float xn  = v * inv;
        const __nv_bfloat16 hi = __float2bfloat16(xn);
        const float lo = xn - __bfloat162float(hi);
        const long long row = (long long)b * 257;
        g_Abf[row * KTOT + c]       = hi;
        g_Abf[row * KTOT + 256 + c] = __float2bfloat16(lo);
        return;
    }

    if (g < 384) {
        // ---- zero pad rows 8224..8319 ----
        const int row = NTOK + (g - 288);
        ((unsigned*)g_Abf)[(long long)row * 256 + tid] = 0u;
        return;
    }

    // ---- codebook rows (already coalesced) ----
    const int wr = g - 384;
    const int c  = tid;
    if (c == 0) g_used[wr] = 0;
    const float v   = W[wr * WIDTH + c];
    const float s   = block_reduce_sum_256(v * v);
    const float inv = 1.f / fmaxf(sqrtf(s), 1e-12f);
    const float xn  = v * inv;
    const __nv_bfloat16 hi = __float2bfloat16(xn);
    const float lo = xn - __bfloat162float(hi);
    g_Bbf[(long long)wr * KTOT + c]       = hi;
    g_Bbf[(long long)wr * KTOT + 256 + c] = __float2bfloat16(lo);
}

// ---------------- stage loaders ----------------
// full slab (prologue only; commits internally)
__device__ __forceinline__ void load_slab(unsigned sb, int bm, int bn,
                                          int kA0, int kB0, int tid) {
    const int ck = tid & 7;
    const int r0 = tid >> 3;
    const unsigned cswz = (unsigned)(ck << 4);
    #pragma unroll
    for (int i = 0; i < 4; i++) {
        const int lr = r0 + 32 * i;
        const unsigned off = (unsigned)lr * 128u + (cswz ^ (((unsigned)lr & 7u) << 4));
        cp16(sb + off,         g_Abf + (long long)(bm + lr) * KTOT + kA0 + ck * 8);
        cp16(sb + B_OFF + off, g_Bbf + (long long)(bn + lr) * KTOT + kB0 + ck * 8);
    }
    CP_COMMIT();
}
// one quarter of a slab (rows r0+32i for chunk i); caller commits once per iteration
__device__ __forceinline__ void load_chunk(unsigned sb, int bm, int bn,
                                           int kA0, int kB0, int tid, int i) {
    const int ck = tid & 7;
    const int r0 = tid >> 3;
    const unsigned cswz = (unsigned)(ck << 4);
    const int lr = r0 + 32 * i;
    const unsigned off = (unsigned)lr * 128u + (cswz ^ (((unsigned)lr & 7u) << 4));
    cp16(sb + off,         g_Abf + (long long)(bm + lr) * KTOT + kA0 + ck * 8);
    cp16(sb + B_OFF + off, g_Bbf + (long long)(bn + lr) * KTOT + kB0 + ck * 8);
}

// ---------------- K2: bf16 mma.sync GEMM (3-term hi/lo split) + argmax ----------------
// CTA 128x128, 8 warps 2(m) x 4(n), warp tile 64x32; 3-stage ring, 1 sync/slab,
// refill spread across the 4 k16 compute groups (LSU burst smoothing).
__global__ __launch_bounds__(256, 2)
void k_gemm_mma() {
    extern __shared__ char dsm[];

    const unsigned base = smem_u32(dsm);
    const int tid  = threadIdx.x;
    const int lane = tid & 31;
    const int warp = tid >> 5;
    const int wm   = (warp >> 2) * 64;       // warp m-base (2 warps in m)
    const int wn   = (warp & 3) * 32;        // warp n-base (4 warps in n)
    const int bn   = blockIdx.x * TN;
    const int bm   = blockIdx.y * TM;

    float d[4][4][4];
    #pragma unroll
    for (int i = 0; i < 4; i++)
        #pragma unroll
        for (int j = 0; j < 4; j++)
            #pragma unroll
            for (int k = 0; k < 4; k++) d[i][j][k] = 0.f;

    // ldmatrix lane addressing
    const int lsel = lane & 7;
    const int agrp_r = ((lane >> 3) & 1) * 8;   // A: matrices 1,3 -> +8 rows
    const int agrp_k = ((lane >> 4) & 1) * 16;  // A: matrices 2,3 -> +16B k
    const int bgrp_r = ((lane >> 4) & 1) * 8;   // B: matrices 2,3 -> +8 rows
    const int bgrp_k = ((lane >> 3) & 1) * 16;  // B: matrices 1,3 -> +16B k

    // prologue: slabs 0 and 1 into stages 0,1
    {
        int kA, kB;
        slab_off(0, kA, kB); load_slab(base,         bm, bn, kA, kB, tid);
        slab_off(1, kA, kB); load_slab(base + STAGE, bm, bn, kA, kB, tid);
    }

    int s_cur = 0, s_nxt = 2;           // stage of slab t, stage for slab t+2
    #pragma unroll 1
    for (int t = 0; t < NSLAB; t++) {
        const unsigned sA = base + s_cur * STAGE;
        const unsigned sB = sA + B_OFF;
        if (t < NSLAB - 1) CP_WAIT1(); else CP_WAIT0();   // slab t resident
        __syncthreads();   // everyone done reading the stage refilled below

        const int refill = (t + 2 < NSLAB);
        int kA2 = 0, kB2 = 0;
        unsigned pf = base + s_nxt * STAGE;
        if (refill) slab_off(t + 2, kA2, kB2);
        if (++s_cur == NSTAGE) s_cur = 0;
        if (++s_nxt == NSTAGE) s_nxt = 0;

        #pragma unroll
        for (int g = 0; g < 4; g++) {           // k16 groups within 64-k slab
            if (refill) load_chunk(pf, bm, bn, kA2, kB2, tid, g);  // 2 cp16/thread/group
            const int kb = g * 32;
            unsigned a[4][4], b[4][2];
            #pragma unroll
            for (int mt = 0; mt < 4; mt++) {
                const int row = wm + mt * 16 + lsel + agrp_r;
                const int kk  = kb + agrp_k;
                ldsm4(a[mt][0], a[mt][1], a[mt][2], a[mt][3],
                      sA + (unsigned)row * 128u + ((unsigned)kk ^ (((unsigned)row & 7u) << 4)));
            }
            #pragma unroll
            for (int np = 0; np < 2; np++) {
                const int row = wn + np * 16 + lsel + bgrp_r;
                const int kk  = kb + bgrp_k;
                unsigned r0, r1, r2, r3;
                ldsm4(r0, r1, r2, r3,
                      sB + (unsigned)row * 128u + ((unsigned)kk ^ (((unsigned)row & 7u) << 4)));
                b[np * 2 + 0][0] = r0; b[np * 2 + 0][1] = r1;
                b[np * 2 + 1][0] = r2; b[np * 2 + 1][1] = r3;
            }
            #pragma unroll
            for (int mt = 0; mt < 4; mt++)
                #pragma unroll
                for (int nt = 0; nt < 4; nt++)
                    mma_bf16(d[mt][nt], a[mt], b[nt]);
        }
        CP_COMMIT();   // one group per iteration (empty on tail iters keeps WAIT1 invariant)
    }

    // ---- fused argmax epilogue: quad shuffle-reduce + direct global atomicMax ----
    #pragma unroll
    for (int mt = 0; mt < 4; mt++) {
        #pragma unroll
        for (int rh = 0; rh < 2; rh++) {        // d0/d1 = row, d2/d3 = row+8
            float bestv = -2.0f; int bestc = 0;
            #pragma unroll
            for (int nt = 0; nt < 4; nt++) {
                const int c0 = wn + nt * 8 + (lane & 3) * 2;  // ascending col order
                const float v0 = d[mt][nt][rh * 2 + 0];
                const float v1 = d[mt][nt][rh * 2 + 1];
                if (v0 > bestv) { bestv = v0; bestc = c0; }
                if (v1 > bestv) { bestv = v1; bestc = c0 + 1; }
            }
            unsigned long long pk =
                ((unsigned long long)f2key(bestv) << 32) |
                (unsigned long long)(0xFFFFFFFFu - (unsigned)(bn + bestc));
            unsigned long long o1 = __shfl_xor_sync(0xffffffffu, pk, 1);
            if (o1 > pk) pk = o1;
            unsigned long long o2 = __shfl_xor_sync(0xffffffffu, pk, 2);
            if (o2 > pk) pk = o2;
            if ((lane & 3) == 0) {
                const int grow = bm + wm + mt * 16 + rh * 8 + (lane >> 2);
                if (grow < NTOK) atomicMax(&g_best[grow], pk);
            }
        }
    }
}

// ---------------- K3: gather W[idx], outputs, loss + usage; last block finalizes ----------------
// grid = NTOK/4 blocks, 256 threads; block handles tokens 4i..4i+3 (4 MLP chains)
__global__ void k_output(const float* __restrict__ cls,
                         const float* __restrict__ patch,
                         const float* __restrict__ W,
                         float* __restrict__ out) {
    __shared__ unsigned s_last;
    const int c = threadIdx.x;
    float ssum = 0.f;

    #pragma unroll
    for (int q = 0; q < 4; q++) {
        const int t = blockIdx.x * 4 + q;
        const int b = t / 257, j = t % 257;
        const int code = (int)(0xFFFFFFFFu - (unsigned)(g_best[t] & 0xFFFFFFFFull));
        const float w = W[code * WIDTH + c];
        const float x = (j == 0) ? cls[b * WIDTH + c]
                                 : patch[b * 65536 + c * 256 + (j - 1)];
        const float dd = w - x;
        ssum += dd * dd;
        if (c == 0) g_used[code] = 1;
        if (j == 0) out[b * WIDTH + c] = w;
        else        out[8192 + b * 65536 + c * 256 + (j - 1)] = w;
    }
    const float s = block_reduce_sum_256(ssum);
    if (c == 0) atomicAdd(&g_loss, (double)s);

    // ---- last-block-done: fold finalize here ----
    __syncthreads();
    if (c == 0) {
        __threadfence();
        s_last = (atomicAdd(&g_done, 1u) == (unsigned)(gridDim.x - 1)) ? 1u : 0u;
    }
    __syncthreads();
    if (s_last) {
        __threadfence();
        int cnt = 0;
        for (int i = c; i < VOCAB; i += 256) cnt += g_used[i];
        const float cs = block_reduce_sum_256((float)cnt);   // exact for <= 16384
        if (c == 0) {
            out[2105344] = (float)(1.25 * g_loss / (double)(NTOK * WIDTH));
            out[2105345] = 100.0f * cs / (float)VOCAB;
        }
    }
}

// ---------------- launch ----------------
extern "C" void kernel_launch(void* const* d_in, const int* in_sizes, int n_in,
                              void* d_out, int out_size) {
    const float* cls   = nullptr;
    const float* patch = nullptr;
    const float* W     = nullptr;
    for (int i = 0; i < n_in; i++) {
        if      (in_sizes[i] == NBATCH * WIDTH)          cls   = (const float*)d_in[i];
        else if (in_sizes[i] == NBATCH * WIDTH * 256)    patch = (const float*)d_in[i];
        else if (in_sizes[i] == VOCAB * WIDTH)           W     = (const float*)d_in[i];
    }
    float* out = (float*)d_out;

    cudaFuncSetAttribute(k_gemm_mma, cudaFuncAttributeMaxDynamicSharedMemorySize, DYN_SMEM);

    k_normalize<<<384 + VOCAB, 256>>>(cls, patch, W);
    dim3 grid(VOCAB / TN, MPAD / TM);   // (128, 65)
    k_gemm_mma<<<grid, 256, DYN_SMEM>>>();
    k_output<<<NTOK / 4, 256>>>(cls, patch, W, out);
}

// round 17
// speedup vs baseline: 1.0427x; 1.0427x over previous
#include <cuda_runtime.h>
#include <cuda_bf16.h>

#define VOCAB   16384
#define WIDTH   256
#define NTOK    8224      // 32 * 257
#define MPAD    8320      // 65 * 128
#define NBATCH  32

#define KTOT    512       // stored per row: [hi(256) | lo(256)]
#define TM      128
#define TN      128
#define NSLAB   12        // 4x hi*hi + 4x hi*lo + 4x lo*hi
#define STAGE   32768     // A 16KB + B 16KB
#define B_OFF   16384
#define NSTAGE  3
#define DYN_SMEM (NSTAGE * STAGE)   // 96KB -> 2 CTAs/SM

// ---------------- scratch (device globals; no runtime alloc) ----------------
__device__ __align__(16) __nv_bfloat16 g_Abf[MPAD * KTOT];    // 8.5 MB
__device__ __align__(16) __nv_bfloat16 g_Bbf[VOCAB * KTOT];   // 16.8 MB
__device__ unsigned long long  g_best[NTOK];
__device__ int                 g_used[VOCAB];
__device__ double              g_loss;
__device__ unsigned            g_done;

// ---------------- helpers ----------------
__device__ __forceinline__ float block_reduce_sum_256(float v) {
    __shared__ float red[8];
    const int lane = threadIdx.x & 31;
    const int w    = threadIdx.x >> 5;
    #pragma unroll
    for (int o = 16; o > 0; o >>= 1) v += __shfl_xor_sync(0xffffffffu, v, o);
    if (lane == 0) red[w] = v;
    __syncthreads();
    float s = 0.f;
    #pragma unroll
    for (int i = 0; i < 8; i++) s += red[i];
    return s;
}
__device__ __forceinline__ unsigned int f2key(float v) {
    unsigned int u = __float_as_uint(v);
    return (u & 0x80000000u) ? ~u : (u | 0x80000000u);
}
__device__ __forceinline__ unsigned smem_u32(const void* p) {
    unsigned a;
    asm("{ .reg .u64 t; cvta.to.shared.u64 t, %1; cvt.u32.u64 %0, t; }" : "=r"(a) : "l"(p));
    return a;
}
__device__ __forceinline__ void cp16(unsigned dst, const void* src) {
    asm volatile("cp.async.cg.shared.global [%0], [%1], 16;" :: "r"(dst), "l"(src));
}
#define CP_COMMIT() asm volatile("cp.async.commit_group;" ::: "memory")
#define CP_WAIT1()  asm volatile("cp.async.wait_group 1;"  ::: "memory")
#define CP_WAIT0()  asm volatile("cp.async.wait_group 0;"  ::: "memory")

__device__ __forceinline__ void ldsm4(unsigned& r0, unsigned& r1, unsigned& r2, unsigned& r3,
                                      unsigned addr) {
    asm volatile("ldmatrix.sync.aligned.m8n8.x4.shared.b16 {%0,%1,%2,%3}, [%4];"
                 : "=r"(r0), "=r"(r1), "=r"(r2), "=r"(r3) : "r"(addr));
}
__device__ __forceinline__ void mma_bf16(float* d, const unsigned* a, const unsigned* b) {
    asm volatile(
        "mma.sync.aligned.m16n8k16.row.col.f32.bf16.bf16.f32 "
        "{%0,%1,%2,%3}, {%4,%5,%6,%7}, {%8,%9}, {%0,%1,%2,%3};"
        : "+f"(d[0]), "+f"(d[1]), "+f"(d[2]), "+f"(d[3])
        : "r"(a[0]), "r"(a[1]), "r"(a[2]), "r"(a[3]), "r"(b[0]), "r"(b[1]));
}

// slab t -> (A k-offset, B k-offset) in bf16 elements within a row
__device__ __forceinline__ void slab_off(int t, int& kA, int& kB) {
    kA = (t < 8) ? ((t & 3) << 6) : (((t - 8) << 6) + 256);            // hi,hi,lo
    kB = (t < 4) ? (t << 6) : ((t < 8) ? (((t - 4) << 6) + 256)        // hi,lo,hi
                                       : ((t - 8) << 6));
}

// ---------------- K1: gather + normalize + bf16 hi/lo split (+ state reset) ----------------
// grid: [0,256) patch tile blocks (b, jg); [256,288) class tokens; [288,384) zero pad rows;
//       [384, 384+VOCAB) codebook rows.
__global__ void k_normalize(const float* __restrict__ cls,
                            const float* __restrict__ patch,
                            const float* __restrict__ W) {
    const int g   = blockIdx.x;
    const int tid = threadIdx.x;

    if (g < 256) {
        // ---- patch tokens: coalesced along j (two passes), smem transpose ----
        __shared__ float s_part[8][32];
        __shared__ float s_inv[32];
        __shared__ __nv_bfloat16 s_row[32][514];   // 257-word row stride: conflict-free
        const int b  = g >> 3;
        const int j0 = (g & 7) * 32;
        const int w = tid >> 5, lane = tid & 31;
        // fold g_best reset here (256*256 threads cover NTOK)
        const int gid = g * 256 + tid;
        if (gid < NTOK) g_best[gid] = 0ull;

        const float* psrc = patch + b * 65536 + j0;   // (c, j0+lane) at c*256 + lane
        float ss = 0.f;
        #pragma unroll 4
        for (int i = 0; i < 32; i++) {
            const float v = psrc[(w * 32 + i) * 256 + lane];
            ss += v * v;
        }
        s_part[w][lane] = ss;
        __syncthreads();
        if (w == 0) {
            float t = 0.f;
            #pragma unroll
            for (int i = 0; i < 8; i++) t += s_part[i][lane];
            s_inv[lane] = 1.f / fmaxf(sqrtf(t), 1e-12f);
        }
        __syncthreads();
        const float inv = s_inv[lane];
        #pragma unroll 4
        for (int i = 0; i < 32; i++) {
            const int c = w * 32 + i;
            const float v  = psrc[c * 256 + lane];
            const float xn = v * inv;
            const __nv_bfloat16 hi = __float2bfloat16(xn);
            const float lo = xn - __bfloat162float(hi);
            s_row[lane][c]       = hi;
            s_row[lane][256 + c] = __float2bfloat16(lo);
        }
        __syncthreads();
        // 32 contiguous A rows: linear coalesced copy (1 word/thread/row)
        unsigned* dw = (unsigned*)(g_Abf + (long long)(b * 257 + 1 + j0) * KTOT);
        #pragma unroll 8
        for (int row = 0; row < 32; row++)
            dw[row * 256 + tid] = *(const unsigned*)&s_row[row][tid * 2];
        return;
    }

    if (g < 288) {
        // ---- class tokens (32 rows, tiny) ----
        const int b = g - 256;
        const int c = tid;
        if (b == 0) {
            if (c == 1) g_loss = 0.0;
            if (c == 2) g_done = 0u;
        }
        const float v   = cls[b * WIDTH + c];
        const float s   = block_reduce_sum_256(v * v);
        const float inv = 1.f / fmaxf(sqrtf(s), 1e-12f);
        const float xn  = v * inv;
        const __nv_bfloat16 hi = __float2bfloat16(xn);
        const float lo = xn - __bfloat162float(hi);
        const long long row = (long long)b * 257;
        g_Abf[row * KTOT + c]       = hi;
        g_Abf[row * KTOT + 256 + c] = __float2bfloat16(lo);
        return;
    }

    if (g < 384) {
        // ---- zero pad rows 8224..8319 ----
        const int row = NTOK + (g - 288);
        ((unsigned*)g_Abf)[(long long)row * 256 + tid] = 0u;
        return;
    }

    // ---- codebook rows (already coalesced) ----
    const int wr = g - 384;
    const int c  = tid;
    if (c == 0) g_used[wr] = 0;
    const float v   = W[wr * WIDTH + c];
    const float s   = block_reduce_sum_256(v * v);
    const float inv = 1.f / fmaxf(sqrtf(s), 1e-12f);
    const float xn  = v * inv;
    const __nv_bfloat16 hi = __float2bfloat16(xn);
    const float lo = xn - __bfloat162float(hi);
    g_Bbf[(long long)wr * KTOT + c]       = hi;
    g_Bbf[(long long)wr * KTOT + 256 + c] = __float2bfloat16(lo);
}

// ---------------- stage loader: one (A-chunk, B-chunk) slab ----------------
__device__ __forceinline__ void load_slab(unsigned sb, int bm, int bn,
                                          int kA0, int kB0, int tid) {
    const int ck = tid & 7;            // 16B chunk (8 bf16) within 128B row
    const int r0 = tid >> 3;           // 0..31
    const unsigned cswz = (unsigned)(ck << 4);
    #pragma unroll
    for (int i = 0; i < 4; i++) {
        const int lr = r0 + 32 * i;
        const unsigned off = (unsigned)lr * 128u + (cswz ^ (((unsigned)lr & 7u) << 4));
        cp16(sb + off,         g_Abf + (long long)(bm + lr) * KTOT + kA0 + ck * 8);
        cp16(sb + B_OFF + off, g_Bbf + (long long)(bn + lr) * KTOT + kB0 + ck * 8);
    }
    CP_COMMIT();
}

// ---------------- K2: bf16 mma.sync GEMM (3-term hi/lo split) + argmax ----------------
// CTA 128x128, 8 warps 2(m) x 4(n), warp tile 64x32; 3-stage ring, 1 sync/slab,
// burst refill right after the barrier (R13-proven local optimum — do not restructure)
__global__ __launch_bounds__(256, 2)
void k_gemm_mma() {
    extern __shared__ char dsm[];

    const unsigned base = smem_u32(dsm);
    const int tid  = threadIdx.x;
    const int lane = tid & 31;
    const int warp = tid >> 5;
    const int wm   = (warp >> 2) * 64;       // warp m-base (2 warps in m)
    const int wn   = (warp & 3) * 32;        // warp n-base (4 warps in n)
    const int bn   = blockIdx.x * TN;
    const int bm   = blockIdx.y * TM;

    float d[4][4][4];
    #pragma unroll
    for (int i = 0; i < 4; i++)
        #pragma unroll
        for (int j = 0; j < 4; j++)
            #pragma unroll
            for (int k = 0; k < 4; k++) d[i][j][k] = 0.f;

    // ldmatrix lane addressing
    const int lsel = lane & 7;
    const int agrp_r = ((lane >> 3) & 1) * 8;   // A: matrices 1,3 -> +8 rows
    const int agrp_k = ((lane >> 4) & 1) * 16;  // A: matrices 2,3 -> +16B k
    const int bgrp_r = ((lane >> 4) & 1) * 8;   // B: matrices 2,3 -> +8 rows
    const int bgrp_k = ((lane >> 3) & 1) * 16;  // B: matrices 1,3 -> +16B k

    // prologue: slabs 0 and 1 into stages 0,1
    {
        int kA, kB;
        slab_off(0, kA, kB); load_slab(base,         bm, bn, kA, kB, tid);
        slab_off(1, kA, kB); load_slab(base + STAGE, bm, bn, kA, kB, tid);
    }

    int s_cur = 0, s_nxt = 2;           // stage of slab t, stage for slab t+2
    #pragma unroll 1
    for (int t = 0; t < NSLAB; t++) {
        const unsigned sA = base + s_cur * STAGE;
        const unsigned sB = sA + B_OFF;
        if (t < NSLAB - 1) CP_WAIT1(); else CP_WAIT0();   // slab t resident
        __syncthreads();   // everyone done reading the stage refilled below

        if (t + 2 < NSLAB) {            // refill stage s_nxt (= stage of slab t-1)
            int kA, kB;
            slab_off(t + 2, kA, kB);
            load_slab(base + s_nxt * STAGE, bm, bn, kA, kB, tid);
        }
        if (++s_cur == NSTAGE) s_cur = 0;
        if (++s_nxt == NSTAGE) s_nxt = 0;

        #pragma unroll
        for (int g = 0; g < 4; g++) {           // k16 groups within 64-k slab
            const int kb = g * 32;
            unsigned a[4][4], b[4][2];
            #pragma unroll
            for (int mt = 0; mt < 4; mt++) {
                const int row = wm + mt * 16 + lsel + agrp_r;
                const int kk  = kb + agrp_k;
                ldsm4(a[mt][0], a[mt][1], a[mt][2], a[mt][3],
                      sA + (unsigned)row * 128u + ((unsigned)kk ^ (((unsigned)row & 7u) << 4)));
            }
            #pragma unroll
            for (int np = 0; np < 2; np++) {
                const int row = wn + np * 16 + lsel + bgrp_r;
                const int kk  = kb + bgrp_k;
                unsigned r0, r1, r2, r3;
                ldsm4(r0, r1, r2, r3,
                      sB + (unsigned)row * 128u + ((unsigned)kk ^ (((unsigned)row & 7u) << 4)));
                b[np * 2 + 0][0] = r0; b[np * 2 + 0][1] = r1;
                b[np * 2 + 1][0] = r2; b[np * 2 + 1][1] = r3;
            }
            #pragma unroll
            for (int mt = 0; mt < 4; mt++)
                #pragma unroll
                for (int nt = 0; nt < 4; nt++)
                    mma_bf16(d[mt][nt], a[mt], b[nt]);
        }
    }

    // ---- fused argmax epilogue: quad shuffle-reduce + direct global atomicMax ----
    #pragma unroll
    for (int mt = 0; mt < 4; mt++) {
        #pragma unroll
        for (int rh = 0; rh < 2; rh++) {        // d0/d1 = row, d2/d3 = row+8
            float bestv = -2.0f; int bestc = 0;
            #pragma unroll
            for (int nt = 0; nt < 4; nt++) {
                const int c0 = wn + nt * 8 + (lane & 3) * 2;  // ascending col order
                const float v0 = d[mt][nt][rh * 2 + 0];
                const float v1 = d[mt][nt][rh * 2 + 1];
                if (v0 > bestv) { bestv = v0; bestc = c0; }
                if (v1 > bestv) { bestv = v1; bestc = c0 + 1; }
            }
            unsigned long long pk =
                ((unsigned long long)f2key(bestv) << 32) |
                (unsigned long long)(0xFFFFFFFFu - (unsigned)(bn + bestc));
            unsigned long long o1 = __shfl_xor_sync(0xffffffffu, pk, 1);
            if (o1 > pk) pk = o1;
            unsigned long long o2 = __shfl_xor_sync(0xffffffffu, pk, 2);
            if (o2 > pk) pk = o2;
            if ((lane & 3) == 0) {
                const int grow = bm + wm + mt * 16 + rh * 8 + (lane >> 2);
                if (grow < NTOK) atomicMax(&g_best[grow], pk);
            }
        }
    }
}

// ---------------- K3: gather W[idx], outputs, loss + usage; last block finalizes ----------------
// grid = NTOK/4 blocks, 256 threads; block handles tokens 4i..4i+3 (4 MLP chains)
__global__ void k_output(const float* __restrict__ cls,
                         const float* __restrict__ patch,
                         const float* __restrict__ W,
                         float* __restrict__ out) {
    __shared__ unsigned s_last;
    const int c = threadIdx.x;
    float ssum = 0.f;

    #pragma unroll
    for (int q = 0; q < 4; q++) {
        const int t = blockIdx.x * 4 + q;
        const int b = t / 257, j = t % 257;
        const int code = (int)(0xFFFFFFFFu - (unsigned)(g_best[t] & 0xFFFFFFFFull));
        const float w = W[code * WIDTH + c];
        const float x = (j == 0) ? cls[b * WIDTH + c]
                                 : patch[b * 65536 + c * 256 + (j - 1)];
        const float dd = w - x;
        ssum += dd * dd;
        if (c == 0) g_used[code] = 1;
        if (j == 0) out[b * WIDTH + c] = w;
        else        out[8192 + b * 65536 + c * 256 + (j - 1)] = w;
    }
    const float s = block_reduce_sum_256(ssum);
    if (c == 0) atomicAdd(&g_loss, (double)s);

    // ---- last-block-done: fold finalize here ----
    __syncthreads();
    if (c == 0) {
        __threadfence();
        s_last = (atomicAdd(&g_done, 1u) == (unsigned)(gridDim.x - 1)) ? 1u : 0u;
    }
    __syncthreads();
    if (s_last) {
        __threadfence();
        int cnt = 0;
        for (int i = c; i < VOCAB; i += 256) cnt += g_used[i];
        const float cs = block_reduce_sum_256((float)cnt);   // exact for <= 16384
        if (c == 0) {
            out[2105344] = (float)(1.25 * g_loss / (double)(NTOK * WIDTH));
            out[2105345] = 100.0f * cs / (float)VOCAB;
        }
    }
}

// ---------------- launch ----------------
extern "C" void kernel_launch(void* const* d_in, const int* in_sizes, int n_in,
                              void* d_out, int out_size) {
    const float* cls   = nullptr;
    const float* patch = nullptr;
    const float* W     = nullptr;
    for (int i = 0; i < n_in; i++) {
        if      (in_sizes[i] == NBATCH * WIDTH)          cls   = (const float*)d_in[i];
        else if (in_sizes[i] == NBATCH * WIDTH * 256)    patch = (const float*)d_in[i];
        else if (in_sizes[i] == VOCAB * WIDTH)           W     = (const float*)d_in[i];
    }
    float* out = (float*)d_out;

    cudaFuncSetAttribute(k_gemm_mma, cudaFuncAttributeMaxDynamicSharedMemorySize, DYN_SMEM);

    k_normalize<<<384 + VOCAB, 256>>>(cls, patch, W);
    dim3 grid(VOCAB / TN, MPAD / TM);   // (128, 65)
    k_gemm_mma<<<grid, 256, DYN_SMEM>>>();
    k_output<<<NTOK / 4, 256>>>(cls, patch, W, out);
}